// round 2
// baseline (speedup 1.0000x reference)
#include <cuda_runtime.h>
#include <cuda_bf16.h>
#include <cstdint>

// Problem constants (match reference)
#define NB      1024      // batch
#define NNODES  10000
#define NROOTS  4
#define MNODES  (NNODES - NROOTS)   // 9996
#define KPAR    4
#define NCONF   16

#define EV_WORDS      313          // ceil(10000/32)
#define EV_WORDS_PAD  320          // padded row stride (16B aligned)

// Bit-packed evidence: 1024 rows x 320 words = 1.31 MB (L2 resident)
__device__ uint32_t g_evbits[NB * EV_WORDS_PAD];

// ---------------------------------------------------------------------------
// Kernel 1: pack evidence int32 (0/1) -> bits via warp ballot.
// One warp packs one 32-bit word per iteration; fully coalesced 40MB stream.
// ---------------------------------------------------------------------------
__global__ void pack_evidence_kernel(const int* __restrict__ ev) {
    const int lane = threadIdx.x & 31;
    const int warps_total = (gridDim.x * blockDim.x) >> 5;
    int wg = (blockIdx.x * blockDim.x + threadIdx.x) >> 5;

    const int total_words = NB * EV_WORDS;
    for (int w = wg; w < total_words; w += warps_total) {
        int b    = w / EV_WORDS;
        int word = w - b * EV_WORDS;
        int idx  = (word << 5) + lane;
        int v = (idx < NNODES) ? ev[(size_t)b * NNODES + idx] : 0;
        unsigned mask = __ballot_sync(0xffffffffu, v & 1);
        if (lane == 0) g_evbits[b * EV_WORDS_PAD + word] = mask;
    }
}

// ---------------------------------------------------------------------------
// Kernel 2: main. Grid = (NCHUNK node-chunks, NB/ROWS row-groups).
// Each block stages ROWS bit-packed evidence rows in SMEM (40KB), then for its
// node chunk: 1 int4 parents load, per row 4 SMEM bit extracts -> conf ->
// cpt gather (L1-hot) -> sigmoid -> coalesced store.
// ---------------------------------------------------------------------------
#define ROWS     32
#define NCHUNK   16
#define NPC      ((MNODES + NCHUNK - 1) / NCHUNK)   // 625 nodes per chunk
#define THREADS  256

__global__ __launch_bounds__(THREADS)
void bayes_main_kernel(const int4*  __restrict__ parents4,
                       const float* __restrict__ root_logits,
                       const float* __restrict__ cpt,
                       float*       __restrict__ out) {
    __shared__ uint32_t sev[ROWS * EV_WORDS_PAD];

    const int chunk = blockIdx.x;       // 0..NCHUNK-1
    const int rg    = blockIdx.y;       // 0..31
    const int tid   = threadIdx.x;
    const int b0    = rg * ROWS;

    // Stage 32 bit-packed rows (40960 B) from L2-resident g_evbits
    const uint32_t* src = g_evbits + (size_t)b0 * EV_WORDS_PAD;
    #pragma unroll 4
    for (int j = tid; j < ROWS * EV_WORDS_PAD; j += THREADS) sev[j] = src[j];

    // Roots: chunk 0 writes the 4 root marginals for its 32 rows
    if (chunk == 0 && tid < ROWS * NROOTS) {
        int r   = tid & (NROOTS - 1);
        int row = tid >> 2;
        float x = root_logits[r];
        out[(size_t)(b0 + row) * NNODES + r] = 1.0f / (1.0f + __expf(-x));
    }
    __syncthreads();

    const int i0   = chunk * NPC;
    const int iend = (i0 + NPC < MNODES) ? (i0 + NPC) : MNODES;

    for (int i = i0 + tid; i < iend; i += THREADS) {
        const int4 p = parents4[i];                 // parents[i][0..3]
        const float* crow = cpt + (size_t)i * NCONF;
        float* obase = out + (size_t)b0 * NNODES + NROOTS + i;

        const int w0 = p.x >> 5, s0 = p.x & 31;
        const int w1 = p.y >> 5, s1 = p.y & 31;
        const int w2 = p.z >> 5, s2 = p.z & 31;
        const int w3 = p.w >> 5, s3 = p.w & 31;

        #pragma unroll 4
        for (int r = 0; r < ROWS; r++) {
            const uint32_t* row = sev + r * EV_WORDS_PAD;
            unsigned conf = (((row[w0] >> s0) & 1u) << 3)
                          | (((row[w1] >> s1) & 1u) << 2)
                          | (((row[w2] >> s2) & 1u) << 1)
                          |  ((row[w3] >> s3) & 1u);
            float x = __ldg(crow + conf);
            float y = 1.0f / (1.0f + __expf(-x));
            obase[(size_t)r * NNODES] = y;
        }
    }
}

// ---------------------------------------------------------------------------
// Launch. Inputs (metadata order): evidence_tensor(int32 B*N), parents(int32
// M*4), root_logits(f32 4), cpt_logits(f32 M*16). Output f32 B*N.
// ---------------------------------------------------------------------------
extern "C" void kernel_launch(void* const* d_in, const int* in_sizes, int n_in,
                              void* d_out, int out_size) {
    const int*   ev      = (const int*)d_in[0];
    const int4*  parents = (const int4*)d_in[1];
    const float* roots   = (const float*)d_in[2];
    const float* cpt     = (const float*)d_in[3];
    float*       out     = (float*)d_out;

    pack_evidence_kernel<<<296, 256>>>(ev);

    dim3 grid(NCHUNK, NB / ROWS);
    bayes_main_kernel<<<grid, THREADS>>>(parents, roots, cpt, out);
}

// round 3
// speedup vs baseline: 2.2978x; 2.2978x over previous
#include <cuda_runtime.h>
#include <cuda_bf16.h>
#include <cstdint>

#define NB      1024
#define NNODES  10000
#define NROOTS  4
#define MNODES  (NNODES - NROOTS)   // 9996
#define NCONF   16
#define NRG     32                  // 1024 rows / 32 bits
#define EVT_STRIDE 10016            // padded node stride

// Transposed bit-packed evidence: g_evt[rg][node], bit r = ev[rg*32+r][node]
__device__ uint32_t g_evt[NRG * EVT_STRIDE];          // 1.28 MB
// Pre-sigmoided CPT: g_sig[i][conf]
__device__ float    g_sig[MNODES * NCONF];            // 640 KB

// ---------------------------------------------------------------------------
// Kernel A: 32x32 tile transpose + ballot pack.
// grid = (313 node-tiles, 32 row-groups), block = 256
// ---------------------------------------------------------------------------
__global__ __launch_bounds__(256)
void pack_t_kernel(const int* __restrict__ ev) {
    __shared__ int tile[32 * 33];
    const int n0  = blockIdx.x * 32;
    const int rg  = blockIdx.y;
    const int b0  = rg * 32;
    const int t   = threadIdx.x;
    const int row = t >> 3;           // 0..31
    const int c4  = (t & 7) << 2;     // 0,4,...,28

    const size_t gbase = (size_t)(b0 + row) * NNODES + n0 + c4;
    if (n0 + 31 < NNODES) {
        int4 v = *(const int4*)(ev + gbase);           // coalesced, aligned
        tile[row * 33 + c4 + 0] = v.x;
        tile[row * 33 + c4 + 1] = v.y;
        tile[row * 33 + c4 + 2] = v.z;
        tile[row * 33 + c4 + 3] = v.w;
    } else {
        #pragma unroll
        for (int j = 0; j < 4; j++) {
            int col = n0 + c4 + j;
            tile[row * 33 + c4 + j] = (col < NNODES) ? ev[gbase + j] : 0;
        }
    }
    __syncthreads();

    const int w = t >> 5, lane = t & 31;
    #pragma unroll
    for (int j = 0; j < 4; j++) {
        int n = w * 4 + j;                             // 0..31
        int v = tile[lane * 33 + n];                   // conflict-free (33 stride)
        unsigned m = __ballot_sync(0xffffffffu, v & 1);
        if (lane == 0 && (n0 + n) < NNODES)
            g_evt[rg * EVT_STRIDE + n0 + n] = m;
    }
}

// ---------------------------------------------------------------------------
// Kernel B: precompute sigmoid of all CPT logits (vectorized float4)
// ---------------------------------------------------------------------------
__global__ __launch_bounds__(256)
void sig_kernel(const float4* __restrict__ cpt4) {
    int idx = blockIdx.x * blockDim.x + threadIdx.x;
    const int total = MNODES * NCONF / 4;              // 39984
    if (idx < total) {
        float4 x = cpt4[idx];
        float4 y;
        y.x = 1.0f / (1.0f + __expf(-x.x));
        y.y = 1.0f / (1.0f + __expf(-x.y));
        y.z = 1.0f / (1.0f + __expf(-x.z));
        y.w = 1.0f / (1.0f + __expf(-x.w));
        ((float4*)g_sig)[idx] = y;
    }
}

// ---------------------------------------------------------------------------
// Kernel C: main. grid = (40 node-tiles, 32 row-groups), block = 256.
// Thread owns node i: 1 int4 parents load, 4 evt gathers (whole 32-row column
// of parent bits), 16 sigmoids -> private SMEM slot, then 32 unrolled rows:
// conf from register bits -> 1 LDS -> 1 coalesced STG.
// ---------------------------------------------------------------------------
#define THREADS 256
#define SLOT    20   // floats per thread slot (16B-aligned, odd-ish banks)

__global__ __launch_bounds__(THREADS)
void bayes_main(const int4*  __restrict__ parents4,
                const float* __restrict__ root_logits,
                float*       __restrict__ out) {
    __shared__ float slot[THREADS * SLOT];             // 20 KB

    const int rg  = blockIdx.y;
    const int b0  = rg * 32;
    const int tid = threadIdx.x;
    const int i   = blockIdx.x * THREADS + tid;

    // Root marginals: first node-tile writes 32 rows x 4 roots
    if (blockIdx.x == 0 && tid < 32 * NROOTS) {
        int r = tid & (NROOTS - 1), row = tid >> 2;
        float x = root_logits[r];
        out[(size_t)(b0 + row) * NNODES + r] = 1.0f / (1.0f + __expf(-x));
    }
    if (i >= MNODES) return;

    const int4 p = parents4[i];
    const uint32_t* __restrict__ evt = g_evt + rg * EVT_STRIDE;
    const uint32_t w0 = evt[p.x];
    const uint32_t w1 = evt[p.y];
    const uint32_t w2 = evt[p.z];
    const uint32_t w3 = evt[p.w];

    // Stage this node's 16 sigmoids into a private SMEM slot (no sync needed)
    float* myslot = slot + tid * SLOT;
    const float4* __restrict__ srow = (const float4*)(g_sig + (size_t)i * NCONF);
    #pragma unroll
    for (int j = 0; j < 4; j++)
        ((float4*)myslot)[j] = srow[j];                // coalesced LDG.128

    float* obase = out + (size_t)b0 * NNODES + NROOTS + i;
    #pragma unroll
    for (int r = 0; r < 32; r++) {
        unsigned conf = (((w0 >> r) & 1u) << 3)
                      | (((w1 >> r) & 1u) << 2)
                      | (((w2 >> r) & 1u) << 1)
                      |  ((w3 >> r) & 1u);
        obase[(size_t)r * NNODES] = myslot[conf];      // LDS + coalesced STG
    }
}

// ---------------------------------------------------------------------------
extern "C" void kernel_launch(void* const* d_in, const int* in_sizes, int n_in,
                              void* d_out, int out_size) {
    const int*    ev      = (const int*)d_in[0];
    const int4*   parents = (const int4*)d_in[1];
    const float*  roots   = (const float*)d_in[2];
    const float4* cpt4    = (const float4*)d_in[3];
    float*        out     = (float*)d_out;

    dim3 gpack((NNODES + 31) / 32, NRG);               // (313, 32)
    pack_t_kernel<<<gpack, 256>>>(ev);

    sig_kernel<<<(MNODES * NCONF / 4 + 255) / 256, 256>>>(cpt4);

    dim3 gmain((MNODES + THREADS - 1) / THREADS, NRG); // (40, 32)
    bayes_main<<<gmain, THREADS>>>(parents, roots, out);
}

// round 4
// speedup vs baseline: 2.9078x; 1.2655x over previous
#include <cuda_runtime.h>
#include <cuda_bf16.h>
#include <cstdint>

#define NB      1024
#define NNODES  10000
#define NROOTS  4
#define MNODES  (NNODES - NROOTS)   // 9996
#define NCONF   16
#define NRG     32                  // 1024 rows / 32-bit words
#define EVT_STRIDE 10016

// Transposed bit-packed evidence: g_evt[rg][node], bit r = ev[rg*32+r][node]
__device__ uint32_t g_evt[NRG * EVT_STRIDE];          // 1.28 MB
// Pre-sigmoided CPT
__device__ float    g_sig[MNODES * NCONF];            // 640 KB

// ---------------------------------------------------------------------------
// Kernel A (fused): blocks [0,316) = register-accumulator bit-transpose pack;
// blocks [316,473) = sigmoid precompute.
// Pack: warp tile = 128 nodes x 32 rows. Lane owns 4 nodes; builds 4 bit-words
// in registers from 32 coalesced int4 row loads; one uint4 store. No smem,
// no ballot, no barrier.
// ---------------------------------------------------------------------------
#define PACK_WARPS   (79 * 32)        // ceil(10000/128) tiles x 32 row-groups
#define PACK_BLOCKS  (PACK_WARPS / 8) // 316 blocks of 8 warps
#define SIG_TOTAL    (MNODES * NCONF / 4)  // 39984 float4
#define SIG_BLOCKS   ((SIG_TOTAL + 255) / 256)

__global__ __launch_bounds__(256)
void pack_sig_kernel(const int* __restrict__ ev, const float4* __restrict__ cpt4) {
    if (blockIdx.x >= PACK_BLOCKS) {
        int idx = (blockIdx.x - PACK_BLOCKS) * 256 + threadIdx.x;
        if (idx < SIG_TOTAL) {
            float4 x = cpt4[idx];
            float4 y;
            y.x = 1.0f / (1.0f + __expf(-x.x));
            y.y = 1.0f / (1.0f + __expf(-x.y));
            y.z = 1.0f / (1.0f + __expf(-x.z));
            y.w = 1.0f / (1.0f + __expf(-x.w));
            ((float4*)g_sig)[idx] = y;
        }
        return;
    }

    const int g    = blockIdx.x * 8 + (threadIdx.x >> 5);  // global warp id
    const int lane = threadIdx.x & 31;
    const int rg   = g & 31;
    const int tile = g >> 5;                                // 0..78
    const int n    = tile * 128 + lane * 4;                 // node base (4 nodes)
    if (n + 3 >= NNODES) return;                            // tail lanes idle

    const int* __restrict__ base = ev + (size_t)(rg * 32) * NNODES + n;
    uint32_t a0 = 0, a1 = 0, a2 = 0, a3 = 0;
    #pragma unroll 8
    for (int r = 0; r < 32; r++) {
        int4 v = *(const int4*)(base + (size_t)r * NNODES);
        a0 |= (uint32_t)(v.x & 1) << r;
        a1 |= (uint32_t)(v.y & 1) << r;
        a2 |= (uint32_t)(v.z & 1) << r;
        a3 |= (uint32_t)(v.w & 1) << r;
    }
    uint4 w = make_uint4(a0, a1, a2, a3);
    *(uint4*)(g_evt + rg * EVT_STRIDE + n) = w;
}

// ---------------------------------------------------------------------------
// Kernel B: main. grid=(40,32), block=256. Thread owns node i within row-group
// rg: 4 evt gathers give parent bits for all 32 rows; 16 sigmoids staged into
// conf-major smem (bank = tid%32 -> conflict-free hot loop); 32 rows of
// conf->LDS->coalesced STG.
// ---------------------------------------------------------------------------
#define THREADS 256

__global__ __launch_bounds__(THREADS)
void bayes_main(const int4*  __restrict__ parents4,
                const float* __restrict__ root_logits,
                float*       __restrict__ out) {
    __shared__ float slot[NCONF * THREADS];   // 16 KB, conf-major

    const int rg  = blockIdx.y;
    const int b0  = rg * 32;
    const int tid = threadIdx.x;
    const int i   = blockIdx.x * THREADS + tid;

    if (blockIdx.x == 0 && tid < 32 * NROOTS) {
        int r = tid & (NROOTS - 1), row = tid >> 2;
        float x = root_logits[r];
        out[(size_t)(b0 + row) * NNODES + r] = 1.0f / (1.0f + __expf(-x));
    }
    if (i >= MNODES) return;

    const int4 p = parents4[i];
    const uint32_t* __restrict__ evt = g_evt + rg * EVT_STRIDE;
    const uint32_t w0 = evt[p.x];
    const uint32_t w1 = evt[p.y];
    const uint32_t w2 = evt[p.z];
    const uint32_t w3 = evt[p.w];

    // Stage 16 pre-sigmoided values, conf-major (no sync: private column)
    const float4* __restrict__ srow = (const float4*)(g_sig + (size_t)i * NCONF);
    #pragma unroll
    for (int j = 0; j < 4; j++) {
        float4 v = srow[j];
        slot[(j * 4 + 0) * THREADS + tid] = v.x;
        slot[(j * 4 + 1) * THREADS + tid] = v.y;
        slot[(j * 4 + 2) * THREADS + tid] = v.z;
        slot[(j * 4 + 3) * THREADS + tid] = v.w;
    }

    float* obase = out + (size_t)b0 * NNODES + NROOTS + i;
    #pragma unroll
    for (int r = 0; r < 32; r++) {
        unsigned conf = (((w0 >> r) & 1u) << 3)
                      | (((w1 >> r) & 1u) << 2)
                      | (((w2 >> r) & 1u) << 1)
                      |  ((w3 >> r) & 1u);
        obase[(size_t)r * NNODES] = slot[conf * THREADS + tid];  // conflict-free
    }
}

// ---------------------------------------------------------------------------
extern "C" void kernel_launch(void* const* d_in, const int* in_sizes, int n_in,
                              void* d_out, int out_size) {
    const int*    ev      = (const int*)d_in[0];
    const int4*   parents = (const int4*)d_in[1];
    const float*  roots   = (const float*)d_in[2];
    const float4* cpt4    = (const float4*)d_in[3];
    float*        out     = (float*)d_out;

    pack_sig_kernel<<<PACK_BLOCKS + SIG_BLOCKS, 256>>>(ev, cpt4);

    dim3 gmain((MNODES + THREADS - 1) / THREADS, NRG);  // (40, 32)
    bayes_main<<<gmain, THREADS>>>(parents, roots, out);
}

// round 5
// speedup vs baseline: 3.2275x; 1.1099x over previous
#include <cuda_runtime.h>
#include <cuda_bf16.h>
#include <cstdint>

#define NB      1024
#define NNODES  10000
#define NROOTS  4
#define MNODES  (NNODES - NROOTS)   // 9996
#define NCONF   16
#define NPAD    10016               // padded node count

// Interleaved transposed bit-pack: g_evi[(rgq*NPAD + node)*4 + q] has bit r =
// evidence[(rgq*4+q)*32 + r][node].  uint4 per node = 128 batch rows.
__device__ uint32_t g_evi[8 * NPAD * 4];     // 1.28 MB
__device__ float    g_sig[MNODES * NCONF];   // 640 KB pre-sigmoided CPT

// ---------------------------------------------------------------------------
// Kernel A (fused pack + sigmoid). Pack: warp tile = 64 nodes x 32 rows.
// Lane owns 2 nodes; builds 2 bit-words from 32 coalesced int2 row loads.
// ---------------------------------------------------------------------------
#define PACK_TILES   157                    // ceil(10000/64)
#define PACK_WARPS   (PACK_TILES * 32)      // x 32 row-groups
#define PACK_BLOCKS  (PACK_WARPS / 8)       // 628
#define SIG_TOTAL    (MNODES * NCONF / 4)   // 39984 float4
#define SIG_BLOCKS   ((SIG_TOTAL + 255) / 256)

__global__ __launch_bounds__(256)
void pack_sig_kernel(const int* __restrict__ ev, const float4* __restrict__ cpt4) {
    if (blockIdx.x >= PACK_BLOCKS) {
        int idx = (blockIdx.x - PACK_BLOCKS) * 256 + threadIdx.x;
        if (idx < SIG_TOTAL) {
            float4 x = cpt4[idx];
            float4 y;
            y.x = 1.0f / (1.0f + __expf(-x.x));
            y.y = 1.0f / (1.0f + __expf(-x.y));
            y.z = 1.0f / (1.0f + __expf(-x.z));
            y.w = 1.0f / (1.0f + __expf(-x.w));
            ((float4*)g_sig)[idx] = y;
        }
        return;
    }

    const int g    = blockIdx.x * 8 + (threadIdx.x >> 5);
    const int lane = threadIdx.x & 31;
    const int rg   = g & 31;
    const int tile = g >> 5;                         // 0..156
    const int n    = tile * 64 + lane * 2;
    if (n >= NNODES) return;                         // NNODES even: pairs never straddle

    const int* __restrict__ base = ev + (size_t)(rg * 32) * NNODES + n;
    uint32_t a0 = 0, a1 = 0;
    #pragma unroll 8
    for (int r = 0; r < 32; r++) {
        int2 v = *(const int2*)(base + (size_t)r * NNODES);
        a0 |= (uint32_t)(v.x & 1) << r;
        a1 |= (uint32_t)(v.y & 1) << r;
    }
    uint32_t* dst = g_evi + ((size_t)(rg >> 2) * NPAD + n) * 4 + (rg & 3);
    dst[0] = a0;
    dst[4] = a1;
}

// ---------------------------------------------------------------------------
// Kernel B: main. grid=(79, 8), block=128. Thread owns node i, row-quad rgq
// (128 batch rows). 4 scattered LDG.128 fetch parent bits for all 128 rows;
// 16 sigmoids staged conf-major in smem (conflict-free); 128 outputs.
// ---------------------------------------------------------------------------
#define THREADS 128

__global__ __launch_bounds__(THREADS)
void bayes_main(const int4*  __restrict__ parents4,
                const float* __restrict__ root_logits,
                float*       __restrict__ out) {
    __shared__ float slot[NCONF * THREADS];          // 8 KB, conf-major

    const int rgq = blockIdx.y;                      // 0..7
    const int b0  = rgq * 128;
    const int tid = threadIdx.x;
    const int i   = blockIdx.x * THREADS + tid;

    // Roots: first node-tile writes 128 rows x 4 roots
    if (blockIdx.x == 0) {
        #pragma unroll
        for (int r = 0; r < NROOTS; r++) {
            float x = root_logits[r];
            out[(size_t)(b0 + tid) * NNODES + r] = 1.0f / (1.0f + __expf(-x));
        }
    }
    if (i >= MNODES) return;

    const int4 p = parents4[i];
    const uint4* __restrict__ evi4 = (const uint4*)(g_evi + (size_t)rgq * NPAD * 4);
    const uint4 wa = evi4[p.x];
    const uint4 wb = evi4[p.y];
    const uint4 wc = evi4[p.z];
    const uint4 wd = evi4[p.w];

    // Stage 16 pre-sigmoided values, conf-major (private column, no sync)
    const float4* __restrict__ srow = (const float4*)(g_sig + (size_t)i * NCONF);
    #pragma unroll
    for (int j = 0; j < 4; j++) {
        float4 v = srow[j];
        slot[(j * 4 + 0) * THREADS + tid] = v.x;
        slot[(j * 4 + 1) * THREADS + tid] = v.y;
        slot[(j * 4 + 2) * THREADS + tid] = v.z;
        slot[(j * 4 + 3) * THREADS + tid] = v.w;
    }

    float* obase = out + (size_t)b0 * NNODES + NROOTS + i;
    #pragma unroll
    for (int q = 0; q < 4; q++) {
        const uint32_t x0 = (&wa.x)[q];
        const uint32_t x1 = (&wb.x)[q];
        const uint32_t x2 = (&wc.x)[q];
        const uint32_t x3 = (&wd.x)[q];
        float* orow = obase + (size_t)(q * 32) * NNODES;
        #pragma unroll
        for (int r = 0; r < 32; r++) {
            unsigned conf = (((x0 >> r) & 1u) << 3)
                          | (((x1 >> r) & 1u) << 2)
                          | (((x2 >> r) & 1u) << 1)
                          |  ((x3 >> r) & 1u);
            orow[(size_t)r * NNODES] = slot[conf * THREADS + tid];
        }
    }
}

// ---------------------------------------------------------------------------
extern "C" void kernel_launch(void* const* d_in, const int* in_sizes, int n_in,
                              void* d_out, int out_size) {
    const int*    ev      = (const int*)d_in[0];
    const int4*   parents = (const int4*)d_in[1];
    const float*  roots   = (const float*)d_in[2];
    const float4* cpt4    = (const float4*)d_in[3];
    float*        out     = (float*)d_out;

    pack_sig_kernel<<<PACK_BLOCKS + SIG_BLOCKS, 256>>>(ev, cpt4);

    dim3 gmain((MNODES + THREADS - 1) / THREADS, 8);   // (79, 8)
    bayes_main<<<gmain, THREADS>>>(parents, roots, out);
}